// round 5
// baseline (speedup 1.0000x reference)
#include <cuda_runtime.h>
#include <cstdint>

#define NN 100000
#define NE 3200000
#define FI 512
#define HH 16
#define BN_EPS 1e-5f

// ---------------- scratch (static device globals; no allocs) ----------------
__device__ int   g_degi[NN];       // in-degree (int)
__device__ int   g_off [NN];       // CSR row start
__device__ int   g_cur [NN];       // CSR fill cursor
__device__ float g_dinv[NN];       // rsqrt(deg+1)
__device__ int   g_src[NE];
__device__ int   g_dst[NE];
__device__ int   g_csr[NE];        // src indices grouped by dst
__device__ float g_hws [NN * HH];  // dinv[n] * (x @ W1)[n]
__device__ float g_agg [NN * HH];  // conv1 output (post-aggregation)
__device__ float g_hw2s[NN * 2];   // dinv[n] * (W2^T relu(bn(agg)))[n]
__device__ float g_bnsum[HH];
__device__ float g_bnsq [HH];
__device__ float g_bna[HH];        // gamma * rsqrt(var+eps)
__device__ float g_bnb[HH];        // beta - mean * bna
__device__ int   g_is64;           // 1 if edge_index is int64, 0 if int32

// ---------------- dtype detection (JAX x64-disabled downcasts int64->int32) -
__global__ void k_detect(const int* __restrict__ ei32) {
    if (threadIdx.x == 0) {
        int nz = 0;
#pragma unroll
        for (int i = 0; i < 64; i++) nz |= ei32[2 * i + 1];
        g_is64 = (nz == 0) ? 1 : 0;
    }
}

__global__ void k_zero_deg() {
    int i = blockIdx.x * blockDim.x + threadIdx.x;
    if (i < NN) g_degi[i] = 0;
}

// decode edge index to int32 + int histogram of dst
__global__ void k_edge_pass1(const void* __restrict__ eiv) {
    int e = blockIdx.x * blockDim.x + threadIdx.x;
    if (e >= NE) return;
    int s, d;
    if (g_is64) {
        const long long* ei = (const long long*)eiv;
        s = (int)ei[e];
        d = (int)ei[(size_t)NE + e];
    } else {
        const int* ei = (const int*)eiv;
        s = ei[e];
        d = ei[(size_t)NE + e];
    }
    if ((unsigned)s >= NN || (unsigned)d >= NN) { s = 0; d = 0; } // fail soft
    g_src[e] = s;
    g_dst[e] = d;
    atomicAdd(&g_degi[d], 1);
}

// ---------------- single-block prefix scan + dinv + bn-zero -----------------
#define SCAN_T 1024
#define SCAN_C 98          // 1024*98 = 100352 >= NN
__global__ void __launch_bounds__(SCAN_T) k_scan() {
    __shared__ int sums[SCAN_T];
    int t = threadIdx.x;
    int lo = t * SCAN_C;
    int hi = lo + SCAN_C; if (hi > NN) hi = NN;
    int s = 0;
    for (int i = lo; i < hi; i++) s += g_degi[i];
    sums[t] = s;
    __syncthreads();
    for (int o = 1; o < SCAN_T; o <<= 1) {
        int v = (t >= o) ? sums[t - o] : 0;
        __syncthreads();
        if (t >= o) sums[t] += v;
        __syncthreads();
    }
    int base = (t == 0) ? 0 : sums[t - 1];
    for (int i = lo; i < hi; i++) {
        g_off[i] = base;
        g_cur[i] = base;
        int dg = g_degi[i];
        base += dg;
        g_dinv[i] = rsqrtf((float)(dg + 1));
    }
    if (t < HH) { g_bnsum[t] = 0.f; g_bnsq[t] = 0.f; }
}

// ---------------- CSR fill ---------------------------------------------------
__global__ void k_fill() {
    int e = blockIdx.x * blockDim.x + threadIdx.x;
    if (e >= NE) return;
    int d = g_dst[e];
    int pos = atomicAdd(&g_cur[d], 1);
    g_csr[pos] = g_src[e];
}

// ---------------- GEMM1: hws = dinv * (x @ W1) -------------------------------
#define TBN 256
#define KC  32
__global__ void __launch_bounds__(128) k_gemm1(const float* __restrict__ x,
                                               const float* __restrict__ W1) {
    __shared__ float xs[TBN][KC + 1];
    __shared__ float w1c[KC * HH];

    const int tid = threadIdx.x;
    const int ft  = tid & 3;
    const int nt  = tid >> 2;
    const int n0  = blockIdx.x * TBN;
    const int nbase = nt * 8;

    float acc[8][4];
#pragma unroll
    for (int i = 0; i < 8; i++)
#pragma unroll
        for (int j = 0; j < 4; j++) acc[i][j] = 0.f;

    for (int kc = 0; kc < FI; kc += KC) {
        __syncthreads();
#pragma unroll
        for (int i = 0; i < 16; i++) {
            int el4 = tid + i * 128;
            int nl  = el4 >> 3;
            int k4  = el4 & 7;
            int gn  = n0 + nl;
            float4 v = make_float4(0.f, 0.f, 0.f, 0.f);
            if (gn < NN)
                v = ((const float4*)(x + (size_t)gn * FI + kc))[k4];
            xs[nl][k4 * 4 + 0] = v.x;
            xs[nl][k4 * 4 + 1] = v.y;
            xs[nl][k4 * 4 + 2] = v.z;
            xs[nl][k4 * 4 + 3] = v.w;
        }
#pragma unroll
        for (int i = 0; i < 4; i++) {
            int el = tid + i * 128;
            w1c[el] = W1[kc * HH + el];
        }
        __syncthreads();

#pragma unroll
        for (int k = 0; k < KC; k++) {
            float4 w = *(const float4*)&w1c[k * HH + ft * 4];
#pragma unroll
            for (int i = 0; i < 8; i++) {
                float xv = xs[nbase + i][k];
                acc[i][0] += xv * w.x;
                acc[i][1] += xv * w.y;
                acc[i][2] += xv * w.z;
                acc[i][3] += xv * w.w;
            }
        }
    }

#pragma unroll
    for (int i = 0; i < 8; i++) {
        int gn = n0 + nbase + i;
        if (gn < NN) {
            float di = g_dinv[gn];
            float4 v = make_float4(di * acc[i][0], di * acc[i][1],
                                   di * acc[i][2], di * acc[i][3]);
            *(float4*)(g_hws + (size_t)gn * HH + ft * 4) = v;
        }
    }
}

// ---------------- agg1: gather over CSR (no atomics) + BN stats --------------
// 4 threads per node (one float4 feature group each).
__global__ void __launch_bounds__(256) k_agg1() {
    __shared__ float ssum[HH], ssq[HH];
    int tid = threadIdx.x;
    if (tid < HH) { ssum[tid] = 0.f; ssq[tid] = 0.f; }
    __syncthreads();

    int gt = blockIdx.x * 256 + tid;
    int n  = gt >> 2;
    int f  = gt & 3;
    if (n < NN) {
        float4 acc = *(const float4*)(g_hws + (size_t)n * HH + f * 4); // self
        int beg = g_off[n];
        int cnt = g_degi[n];
        int k = 0;
        for (; k + 4 <= cnt; k += 4) {
            int s0 = g_csr[beg + k];
            int s1 = g_csr[beg + k + 1];
            int s2 = g_csr[beg + k + 2];
            int s3 = g_csr[beg + k + 3];
            float4 a = *(const float4*)(g_hws + (size_t)s0 * HH + f * 4);
            float4 b = *(const float4*)(g_hws + (size_t)s1 * HH + f * 4);
            float4 c = *(const float4*)(g_hws + (size_t)s2 * HH + f * 4);
            float4 d = *(const float4*)(g_hws + (size_t)s3 * HH + f * 4);
            acc.x += (a.x + b.x) + (c.x + d.x);
            acc.y += (a.y + b.y) + (c.y + d.y);
            acc.z += (a.z + b.z) + (c.z + d.z);
            acc.w += (a.w + b.w) + (c.w + d.w);
        }
        for (; k < cnt; k++) {
            int s = g_csr[beg + k];
            float4 a = *(const float4*)(g_hws + (size_t)s * HH + f * 4);
            acc.x += a.x; acc.y += a.y; acc.z += a.z; acc.w += a.w;
        }
        float di = g_dinv[n];
        acc.x *= di; acc.y *= di; acc.z *= di; acc.w *= di;
        *(float4*)(g_agg + (size_t)n * HH + f * 4) = acc;
        // BN partial sums (per feature)
        atomicAdd(&ssum[f * 4 + 0], acc.x);
        atomicAdd(&ssum[f * 4 + 1], acc.y);
        atomicAdd(&ssum[f * 4 + 2], acc.z);
        atomicAdd(&ssum[f * 4 + 3], acc.w);
        atomicAdd(&ssq [f * 4 + 0], acc.x * acc.x);
        atomicAdd(&ssq [f * 4 + 1], acc.y * acc.y);
        atomicAdd(&ssq [f * 4 + 2], acc.z * acc.z);
        atomicAdd(&ssq [f * 4 + 3], acc.w * acc.w);
    }
    __syncthreads();
    if (tid < HH) {
        atomicAdd(&g_bnsum[tid], ssum[tid]);
        atomicAdd(&g_bnsq[tid],  ssq[tid]);
    }
}

// b1 cancels in BN (constant shift removed by mean subtraction)
__global__ void k_bn_fin(const float* __restrict__ gamma, const float* __restrict__ beta) {
    int f = threadIdx.x;
    if (f >= HH) return;
    float mean = g_bnsum[f] / (float)NN;
    float var  = g_bnsq[f] / (float)NN - mean * mean;
    float a = gamma[f] * rsqrtf(var + BN_EPS);
    g_bna[f] = a;
    g_bnb[f] = beta[f] - mean * a;
}

// ---------------- bn + relu + GEMM2: hw2s = dinv * (W2^T relu(bn(agg))) ------
__global__ void k_fused2(const float* __restrict__ W2) {
    __shared__ float a[HH], b[HH], w2[HH * 2];
    int tid = threadIdx.x;
    if (tid < HH) { a[tid] = g_bna[tid]; b[tid] = g_bnb[tid]; }
    if (tid < HH * 2) w2[tid] = W2[tid];
    __syncthreads();
    int n = blockIdx.x * blockDim.x + tid;
    if (n >= NN) return;
    const float4* hp = (const float4*)(g_agg + (size_t)n * HH);
    float acc0 = 0.f, acc1 = 0.f;
#pragma unroll
    for (int p = 0; p < 4; p++) {
        float4 h = hp[p];
        float v0 = fmaxf(a[p * 4 + 0] * h.x + b[p * 4 + 0], 0.f);
        float v1 = fmaxf(a[p * 4 + 1] * h.y + b[p * 4 + 1], 0.f);
        float v2 = fmaxf(a[p * 4 + 2] * h.z + b[p * 4 + 2], 0.f);
        float v3 = fmaxf(a[p * 4 + 3] * h.w + b[p * 4 + 3], 0.f);
        acc0 += v0 * w2[(p * 4 + 0) * 2] + v1 * w2[(p * 4 + 1) * 2]
              + v2 * w2[(p * 4 + 2) * 2] + v3 * w2[(p * 4 + 3) * 2];
        acc1 += v0 * w2[(p * 4 + 0) * 2 + 1] + v1 * w2[(p * 4 + 1) * 2 + 1]
              + v2 * w2[(p * 4 + 2) * 2 + 1] + v3 * w2[(p * 4 + 3) * 2 + 1];
    }
    float di = g_dinv[n];
    g_hw2s[2 * n]     = di * acc0;
    g_hw2s[2 * n + 1] = di * acc1;
}

// ---------------- layer2 gather + bias + log_softmax -> out ------------------
// 4 threads per node, edges strided by quad lane, shfl reduction.
__global__ void __launch_bounds__(256) k_out(const float* __restrict__ b2,
                                             float* __restrict__ out) {
    int gt = blockIdx.x * 256 + threadIdx.x;
    int n  = gt >> 2;
    int q  = gt & 3;
    float ax = 0.f, ay = 0.f;
    int beg = 0, cnt = 0;
    if (n < NN) {
        beg = g_off[n];
        cnt = g_degi[n];
        if (q == 0) {   // self term once
            float2 v = ((const float2*)g_hw2s)[n];
            ax = v.x; ay = v.y;
        }
        for (int k = q; k < cnt; k += 4) {
            int s = g_csr[beg + k];
            float2 v = ((const float2*)g_hw2s)[s];
            ax += v.x; ay += v.y;
        }
    }
    // quad reduction (lanes n*4..n*4+3 are in the same warp)
    ax += __shfl_xor_sync(0xffffffffu, ax, 1);
    ay += __shfl_xor_sync(0xffffffffu, ay, 1);
    ax += __shfl_xor_sync(0xffffffffu, ax, 2);
    ay += __shfl_xor_sync(0xffffffffu, ay, 2);
    if (n < NN && q == 0) {
        float di = g_dinv[n];
        float z0 = di * ax + b2[0];
        float z1 = di * ay + b2[1];
        float m  = fmaxf(z0, z1);
        float l  = m + logf(expf(z0 - m) + expf(z1 - m));
        out[2 * n]     = z0 - l;
        out[2 * n + 1] = z1 - l;
    }
}

// ---------------- launcher ---------------------------------------------------
extern "C" void kernel_launch(void* const* d_in, const int* in_sizes, int n_in,
                              void* d_out, int out_size) {
    const float* x     = (const float*)d_in[0];
    const void*  ei    = d_in[1];                  // int32 or int64, detected on device
    const float* W1    = (const float*)d_in[2];
    // d_in[3] = b1 : cancels under BN mean subtraction
    const float* gamma = (const float*)d_in[4];
    const float* beta  = (const float*)d_in[5];
    const float* W2    = (const float*)d_in[6];
    const float* b2    = (const float*)d_in[7];
    float* out = (float*)d_out;

    const int TB = 256;
    k_detect    <<<1, 32>>>((const int*)ei);
    k_zero_deg  <<<(NN + TB - 1) / TB, TB>>>();
    k_edge_pass1<<<(NE + TB - 1) / TB, TB>>>(ei);
    k_scan      <<<1, SCAN_T>>>();
    k_fill      <<<(NE + TB - 1) / TB, TB>>>();
    k_gemm1     <<<(NN + TBN - 1) / TBN, 128>>>(x, W1);
    k_agg1      <<<(NN * 4 + TB - 1) / TB, TB>>>();
    k_bn_fin    <<<1, 32>>>(gamma, beta);
    k_fused2    <<<(NN + TB - 1) / TB, TB>>>(W2);
    k_out       <<<(NN * 4 + TB - 1) / TB, TB>>>(b2, out);
}

// round 7
// speedup vs baseline: 1.9682x; 1.9682x over previous
#include <cuda_runtime.h>
#include <cstdint>

#define NN 100000
#define NE 3200000
#define FI 512
#define HH 16
#define BN_EPS 1e-5f
#define NBLK 391            // ceil(NN/256)

// ---------------- scratch (static device globals; no allocs) ----------------
__device__ int   g_degi[NN];       // in-degree (int)
__device__ int   g_off [NN];       // CSR row start
__device__ int   g_cur [NN];       // CSR fill cursor
__device__ float g_dinv[NN];       // rsqrt(deg+1)
__device__ int   g_src[NE];
__device__ int   g_dst[NE];
__device__ int   g_csr[NE];        // src indices grouped by dst
__device__ int   g_bsum [NBLK];    // per-block degree sums
__device__ int   g_bbase[NBLK];    // exclusive prefix of block sums
__device__ float g_hws [NN * HH];  // dinv[n] * (x @ W1)[n]
__device__ float g_agg [NN * HH];  // conv1 output (post-aggregation)
__device__ float g_hw2s[NN * 2];   // dinv[n] * (W2^T relu(bn(agg)))[n]
__device__ float g_bnsum[HH];
__device__ float g_bnsq [HH];
__device__ float g_bna[HH];        // gamma * rsqrt(var+eps)
__device__ float g_bnb[HH];        // beta - mean * bna
__device__ int   g_is64;           // 1 if edge_index is int64, 0 if int32

// ---------------- dtype detection (JAX x64-disabled downcasts int64->int32) -
__global__ void k_detect(const int* __restrict__ ei32) {
    if (threadIdx.x == 0) {
        int nz = 0;
#pragma unroll
        for (int i = 0; i < 64; i++) nz |= ei32[2 * i + 1];
        g_is64 = (nz == 0) ? 1 : 0;
    }
}

__global__ void k_zero_deg() {
    int i = blockIdx.x * blockDim.x + threadIdx.x;
    if (i < NN) g_degi[i] = 0;
}

// decode edge index to int32 + int histogram of dst
__global__ void k_edge_pass1(const void* __restrict__ eiv) {
    int e = blockIdx.x * blockDim.x + threadIdx.x;
    if (e >= NE) return;
    int s, d;
    if (g_is64) {
        const long long* ei = (const long long*)eiv;
        s = (int)ei[e];
        d = (int)ei[(size_t)NE + e];
    } else {
        const int* ei = (const int*)eiv;
        s = ei[e];
        d = ei[(size_t)NE + e];
    }
    if ((unsigned)s >= NN || (unsigned)d >= NN) { s = 0; d = 0; } // fail soft
    g_src[e] = s;
    g_dst[e] = d;
    atomicAdd(&g_degi[d], 1);
}

// ---------------- multi-block prefix scan ------------------------------------
// stage 1: per-block sum of 256 degrees
__global__ void __launch_bounds__(256) k_scan_partial() {
    __shared__ int wsum[8];
    int t = threadIdx.x;
    int i = blockIdx.x * 256 + t;
    int v = (i < NN) ? g_degi[i] : 0;
#pragma unroll
    for (int o = 16; o > 0; o >>= 1) v += __shfl_down_sync(0xffffffffu, v, o);
    if ((t & 31) == 0) wsum[t >> 5] = v;
    __syncthreads();
    if (t < 32) {
        int s = (t < 8) ? wsum[t] : 0;
#pragma unroll
        for (int o = 4; o > 0; o >>= 1) s += __shfl_down_sync(0xffffffffu, s, o);
        if (t == 0) g_bsum[blockIdx.x] = s;
    }
}

// stage 2: one block scans NBLK block sums -> exclusive bases (+ bn zero)
__global__ void __launch_bounds__(512) k_scan_base() {
    __shared__ int wtot[16];
    __shared__ int wpre[16];
    int t = threadIdx.x;
    int lane = t & 31, w = t >> 5;
    int v = (t < NBLK) ? g_bsum[t] : 0;
    int sv = v;
#pragma unroll
    for (int o = 1; o < 32; o <<= 1) {
        int u = __shfl_up_sync(0xffffffffu, sv, o);
        if (lane >= o) sv += u;
    }
    if (lane == 31) wtot[w] = sv;
    __syncthreads();
    if (w == 0) {
        int wv = (lane < 16) ? wtot[lane] : 0;
#pragma unroll
        for (int o = 1; o < 16; o <<= 1) {
            int u = __shfl_up_sync(0xffffffffu, wv, o);
            if (lane >= o) wv += u;
        }
        if (lane < 16) wpre[lane] = wv;
    }
    __syncthreads();
    int base = (w > 0) ? wpre[w - 1] : 0;
    if (t < NBLK) g_bbase[t] = base + sv - v;    // exclusive prefix
    if (t < HH) { g_bnsum[t] = 0.f; g_bnsq[t] = 0.f; }
}

// stage 3: per-block local exclusive scan + base -> off/cur/dinv
__global__ void __launch_bounds__(256) k_scan_write() {
    __shared__ int wtot[8];
    __shared__ int wpre[8];
    int t = threadIdx.x;
    int lane = t & 31, w = t >> 5;
    int i = blockIdx.x * 256 + t;
    int dg = (i < NN) ? g_degi[i] : 0;
    int sv = dg;
#pragma unroll
    for (int o = 1; o < 32; o <<= 1) {
        int u = __shfl_up_sync(0xffffffffu, sv, o);
        if (lane >= o) sv += u;
    }
    if (lane == 31) wtot[w] = sv;
    __syncthreads();
    if (w == 0) {
        int wv = (lane < 8) ? wtot[lane] : 0;
#pragma unroll
        for (int o = 1; o < 8; o <<= 1) {
            int u = __shfl_up_sync(0xffffffffu, wv, o);
            if (lane >= o) wv += u;
        }
        if (lane < 8) wpre[lane] = wv;
    }
    __syncthreads();
    int base = g_bbase[blockIdx.x] + ((w > 0) ? wpre[w - 1] : 0) + sv - dg;
    if (i < NN) {
        g_off[i]  = base;
        g_cur[i]  = base;
        g_dinv[i] = rsqrtf((float)(dg + 1));
    }
}

// ---------------- CSR fill ---------------------------------------------------
__global__ void k_fill() {
    int e = blockIdx.x * blockDim.x + threadIdx.x;
    if (e >= NE) return;
    int d = g_dst[e];
    int pos = atomicAdd(&g_cur[d], 1);
    g_csr[pos] = g_src[e];
}

// ---------------- GEMM1: hws = dinv * (x @ W1) -------------------------------
#define TBN 256
#define KC  32
__global__ void __launch_bounds__(128) k_gemm1(const float* __restrict__ x,
                                               const float* __restrict__ W1) {
    __shared__ float xs[TBN][KC + 1];
    __shared__ float w1c[KC * HH];

    const int tid = threadIdx.x;
    const int ft  = tid & 3;
    const int nt  = tid >> 2;
    const int n0  = blockIdx.x * TBN;
    const int nbase = nt * 8;

    float acc[8][4];
#pragma unroll
    for (int i = 0; i < 8; i++)
#pragma unroll
        for (int j = 0; j < 4; j++) acc[i][j] = 0.f;

    for (int kc = 0; kc < FI; kc += KC) {
        __syncthreads();
#pragma unroll
        for (int i = 0; i < 16; i++) {
            int el4 = tid + i * 128;
            int nl  = el4 >> 3;
            int k4  = el4 & 7;
            int gn  = n0 + nl;
            float4 v = make_float4(0.f, 0.f, 0.f, 0.f);
            if (gn < NN)
                v = ((const float4*)(x + (size_t)gn * FI + kc))[k4];
            xs[nl][k4 * 4 + 0] = v.x;
            xs[nl][k4 * 4 + 1] = v.y;
            xs[nl][k4 * 4 + 2] = v.z;
            xs[nl][k4 * 4 + 3] = v.w;
        }
#pragma unroll
        for (int i = 0; i < 4; i++) {
            int el = tid + i * 128;
            w1c[el] = W1[kc * HH + el];
        }
        __syncthreads();

#pragma unroll
        for (int k = 0; k < KC; k++) {
            float4 w = *(const float4*)&w1c[k * HH + ft * 4];
#pragma unroll
            for (int i = 0; i < 8; i++) {
                float xv = xs[nbase + i][k];
                acc[i][0] += xv * w.x;
                acc[i][1] += xv * w.y;
                acc[i][2] += xv * w.z;
                acc[i][3] += xv * w.w;
            }
        }
    }

#pragma unroll
    for (int i = 0; i < 8; i++) {
        int gn = n0 + nbase + i;
        if (gn < NN) {
            float di = g_dinv[gn];
            float4 v = make_float4(di * acc[i][0], di * acc[i][1],
                                   di * acc[i][2], di * acc[i][3]);
            *(float4*)(g_hws + (size_t)gn * HH + ft * 4) = v;
        }
    }
}

// ---------------- agg1: gather over CSR (no atomics) + BN stats --------------
// 4 threads per node (one float4 group each); quad lanes read the same CSR
// word (warp-broadcast load), no cross-lane shfl -> divergence-safe.
__global__ void __launch_bounds__(256) k_agg1() {
    __shared__ float ssum[HH], ssq[HH];
    int tid = threadIdx.x;
    if (tid < HH) { ssum[tid] = 0.f; ssq[tid] = 0.f; }
    __syncthreads();

    int gt = blockIdx.x * 256 + tid;
    int n  = gt >> 2;
    int f  = gt & 3;
    if (n < NN) {
        float4 acc = *(const float4*)(g_hws + (size_t)n * HH + f * 4); // self
        int beg = g_off[n];
        int cnt = g_degi[n];
        int k = 0;
        for (; k + 4 <= cnt; k += 4) {
            int s0 = g_csr[beg + k];
            int s1 = g_csr[beg + k + 1];
            int s2 = g_csr[beg + k + 2];
            int s3 = g_csr[beg + k + 3];
            float4 a = *(const float4*)(g_hws + (size_t)s0 * HH + f * 4);
            float4 b = *(const float4*)(g_hws + (size_t)s1 * HH + f * 4);
            float4 c = *(const float4*)(g_hws + (size_t)s2 * HH + f * 4);
            float4 d = *(const float4*)(g_hws + (size_t)s3 * HH + f * 4);
            acc.x += (a.x + b.x) + (c.x + d.x);
            acc.y += (a.y + b.y) + (c.y + d.y);
            acc.z += (a.z + b.z) + (c.z + d.z);
            acc.w += (a.w + b.w) + (c.w + d.w);
        }
        for (; k < cnt; k++) {
            int s = g_csr[beg + k];
            float4 a = *(const float4*)(g_hws + (size_t)s * HH + f * 4);
            acc.x += a.x; acc.y += a.y; acc.z += a.z; acc.w += a.w;
        }
        float di = g_dinv[n];
        acc.x *= di; acc.y *= di; acc.z *= di; acc.w *= di;
        *(float4*)(g_agg + (size_t)n * HH + f * 4) = acc;
        atomicAdd(&ssum[f * 4 + 0], acc.x);
        atomicAdd(&ssum[f * 4 + 1], acc.y);
        atomicAdd(&ssum[f * 4 + 2], acc.z);
        atomicAdd(&ssum[f * 4 + 3], acc.w);
        atomicAdd(&ssq [f * 4 + 0], acc.x * acc.x);
        atomicAdd(&ssq [f * 4 + 1], acc.y * acc.y);
        atomicAdd(&ssq [f * 4 + 2], acc.z * acc.z);
        atomicAdd(&ssq [f * 4 + 3], acc.w * acc.w);
    }
    __syncthreads();
    if (tid < HH) {
        atomicAdd(&g_bnsum[tid], ssum[tid]);
        atomicAdd(&g_bnsq[tid],  ssq[tid]);
    }
}

// b1 cancels in BN (constant shift removed by mean subtraction)
__global__ void k_bn_fin(const float* __restrict__ gamma, const float* __restrict__ beta) {
    int f = threadIdx.x;
    if (f >= HH) return;
    float mean = g_bnsum[f] / (float)NN;
    float var  = g_bnsq[f] / (float)NN - mean * mean;
    float a = gamma[f] * rsqrtf(var + BN_EPS);
    g_bna[f] = a;
    g_bnb[f] = beta[f] - mean * a;
}

// ---------------- bn + relu + GEMM2: hw2s = dinv * (W2^T relu(bn(agg))) ------
__global__ void k_fused2(const float* __restrict__ W2) {
    __shared__ float a[HH], b[HH], w2[HH * 2];
    int tid = threadIdx.x;
    if (tid < HH) { a[tid] = g_bna[tid]; b[tid] = g_bnb[tid]; }
    if (tid < HH * 2) w2[tid] = W2[tid];
    __syncthreads();
    int n = blockIdx.x * blockDim.x + tid;
    if (n >= NN) return;
    const float4* hp = (const float4*)(g_agg + (size_t)n * HH);
    float acc0 = 0.f, acc1 = 0.f;
#pragma unroll
    for (int p = 0; p < 4; p++) {
        float4 h = hp[p];
        float v0 = fmaxf(a[p * 4 + 0] * h.x + b[p * 4 + 0], 0.f);
        float v1 = fmaxf(a[p * 4 + 1] * h.y + b[p * 4 + 1], 0.f);
        float v2 = fmaxf(a[p * 4 + 2] * h.z + b[p * 4 + 2], 0.f);
        float v3 = fmaxf(a[p * 4 + 3] * h.w + b[p * 4 + 3], 0.f);
        acc0 += v0 * w2[(p * 4 + 0) * 2] + v1 * w2[(p * 4 + 1) * 2]
              + v2 * w2[(p * 4 + 2) * 2] + v3 * w2[(p * 4 + 3) * 2];
        acc1 += v0 * w2[(p * 4 + 0) * 2 + 1] + v1 * w2[(p * 4 + 1) * 2 + 1]
              + v2 * w2[(p * 4 + 2) * 2 + 1] + v3 * w2[(p * 4 + 3) * 2 + 1];
    }
    float di = g_dinv[n];
    g_hw2s[2 * n]     = di * acc0;
    g_hw2s[2 * n + 1] = di * acc1;
}

// ---------------- layer2 gather + bias + log_softmax -> out ------------------
__global__ void __launch_bounds__(256) k_out(const float* __restrict__ b2,
                                             float* __restrict__ out) {
    int gt = blockIdx.x * 256 + threadIdx.x;
    int n  = gt >> 2;
    int q  = gt & 3;
    float ax = 0.f, ay = 0.f;
    if (n < NN) {
        int beg = g_off[n];
        int cnt = g_degi[n];
        if (q == 0) {   // self term once
            float2 v = ((const float2*)g_hw2s)[n];
            ax = v.x; ay = v.y;
        }
        for (int k = q; k < cnt; k += 4) {
            int s = g_csr[beg + k];
            float2 v = ((const float2*)g_hw2s)[s];
            ax += v.x; ay += v.y;
        }
    }
    // all lanes converged here; quad lanes live in one warp
    ax += __shfl_xor_sync(0xffffffffu, ax, 1);
    ay += __shfl_xor_sync(0xffffffffu, ay, 1);
    ax += __shfl_xor_sync(0xffffffffu, ax, 2);
    ay += __shfl_xor_sync(0xffffffffu, ay, 2);
    if (n < NN && q == 0) {
        float di = g_dinv[n];
        float z0 = di * ax + b2[0];
        float z1 = di * ay + b2[1];
        float m  = fmaxf(z0, z1);
        float l  = m + logf(expf(z0 - m) + expf(z1 - m));
        out[2 * n]     = z0 - l;
        out[2 * n + 1] = z1 - l;
    }
}

// ---------------- launcher ---------------------------------------------------
extern "C" void kernel_launch(void* const* d_in, const int* in_sizes, int n_in,
                              void* d_out, int out_size) {
    const float* x     = (const float*)d_in[0];
    const void*  ei    = d_in[1];                  // int32 or int64, detected on device
    const float* W1    = (const float*)d_in[2];
    // d_in[3] = b1 : cancels under BN mean subtraction
    const float* gamma = (const float*)d_in[4];
    const float* beta  = (const float*)d_in[5];
    const float* W2    = (const float*)d_in[6];
    const float* b2    = (const float*)d_in[7];
    float* out = (float*)d_out;

    const int TB = 256;
    k_detect      <<<1, 32>>>((const int*)ei);
    k_zero_deg    <<<NBLK, TB>>>();
    k_edge_pass1  <<<(NE + TB - 1) / TB, TB>>>(ei);
    k_scan_partial<<<NBLK, TB>>>();
    k_scan_base   <<<1, 512>>>();
    k_scan_write  <<<NBLK, TB>>>();
    k_fill        <<<(NE + TB - 1) / TB, TB>>>();
    k_gemm1       <<<(NN + TBN - 1) / TBN, 128>>>(x, W1);
    k_agg1        <<<(NN * 4 + TB - 1) / TB, TB>>>();
    k_bn_fin      <<<1, 32>>>(gamma, beta);
    k_fused2      <<<(NN + TB - 1) / TB, TB>>>(W2);
    k_out         <<<(NN * 4 + TB - 1) / TB, TB>>>(b2, out);
}

// round 8
// speedup vs baseline: 2.1285x; 1.0814x over previous
#include <cuda_runtime.h>
#include <cstdint>

#define NN 100000
#define NE 3200000
#define FI 512
#define HH 16
#define BN_EPS 1e-5f
#define NBLK 391            // ceil(NN/256)

// ---------------- scratch (static device globals; no allocs) ----------------
__device__ int   g_degi[NN];       // in-degree (int)
__device__ int   g_off [NN];       // CSR row start
__device__ int   g_cur [NN];       // CSR fill cursor
__device__ float g_dinv[NN];       // rsqrt(deg+1)
__device__ int   g_src[NE];
__device__ int   g_dst[NE];
__device__ int   g_csr[NE];        // src indices grouped by dst
__device__ int   g_bsum [NBLK];    // per-block degree sums
__device__ float g_hws [NN * HH];  // dinv[n] * (x @ W1)[n]
__device__ float g_agg [NN * HH];  // conv1 output (post-aggregation)
__device__ float g_hw2s[NN * 2];   // dinv[n] * (W2^T relu(bn(agg)))[n]
__device__ float g_bnsum[HH];
__device__ float g_bnsq [HH];
__device__ int   g_is64;           // 1 if edge_index is int64, 0 if int32

// ---------------- setup: zero degree + dtype detection -----------------------
// (JAX x64-disabled silently downcasts int64->int32; detect on device)
__global__ void __launch_bounds__(256) k_setup(const int* __restrict__ ei32) {
    int i = blockIdx.x * 256 + threadIdx.x;
    if (i < NN) g_degi[i] = 0;
    if (blockIdx.x == 0 && threadIdx.x == 0) {
        int nz = 0;
#pragma unroll
        for (int j = 0; j < 64; j++) nz |= ei32[2 * j + 1];
        g_is64 = (nz == 0) ? 1 : 0;
    }
}

// decode edge index (2 edges/thread) + int histogram of dst
__global__ void __launch_bounds__(256) k_edge_pass1(const void* __restrict__ eiv) {
    int e = (blockIdx.x * 256 + threadIdx.x) * 2;
    if (e >= NE) return;
    int s0, d0, s1, d1;
    if (g_is64) {
        const longlong2* es = (const longlong2*)((const long long*)eiv + e);
        const longlong2* ed = (const longlong2*)((const long long*)eiv + NE + e);
        longlong2 sv = *es, dv = *ed;
        s0 = (int)sv.x; s1 = (int)sv.y;
        d0 = (int)dv.x; d1 = (int)dv.y;
    } else {
        int2 sv = *(const int2*)((const int*)eiv + e);
        int2 dv = *(const int2*)((const int*)eiv + NE + e);
        s0 = sv.x; s1 = sv.y; d0 = dv.x; d1 = dv.y;
    }
    if ((unsigned)s0 >= NN || (unsigned)d0 >= NN) { s0 = 0; d0 = 0; }
    if ((unsigned)s1 >= NN || (unsigned)d1 >= NN) { s1 = 0; d1 = 0; }
    *(int2*)(g_src + e) = make_int2(s0, s1);
    *(int2*)(g_dst + e) = make_int2(d0, d1);
    atomicAdd(&g_degi[d0], 1);
    atomicAdd(&g_degi[d1], 1);
}

// ---------------- scan stage 1: per-block sums -------------------------------
__global__ void __launch_bounds__(256) k_scan_partial() {
    __shared__ int wsum[8];
    int t = threadIdx.x;
    int i = blockIdx.x * 256 + t;
    int v = (i < NN) ? g_degi[i] : 0;
#pragma unroll
    for (int o = 16; o > 0; o >>= 1) v += __shfl_down_sync(0xffffffffu, v, o);
    if ((t & 31) == 0) wsum[t >> 5] = v;
    __syncthreads();
    if (t < 32) {
        int s = (t < 8) ? wsum[t] : 0;
#pragma unroll
        for (int o = 4; o > 0; o >>= 1) s += __shfl_down_sync(0xffffffffu, s, o);
        if (t == 0) g_bsum[blockIdx.x] = s;
    }
}

// ---------------- scan stage 2: base-from-bsum + local scan -> off/cur/dinv --
__global__ void __launch_bounds__(256) k_scan_write() {
    __shared__ int wtot[8];
    __shared__ int wpre[8];
    __shared__ int blkbase;
    int t = threadIdx.x;
    int lane = t & 31, w = t >> 5;
    int bid = blockIdx.x;

    // sum of all block sums before this block (g_bsum complete from stage 1)
    int ps = 0;
    for (int j = t; j < bid; j += 256) ps += g_bsum[j];
#pragma unroll
    for (int o = 16; o > 0; o >>= 1) ps += __shfl_down_sync(0xffffffffu, ps, o);
    if (lane == 0) wtot[w] = ps;
    __syncthreads();
    if (t < 32) {
        int s = (t < 8) ? wtot[t] : 0;
#pragma unroll
        for (int o = 4; o > 0; o >>= 1) s += __shfl_down_sync(0xffffffffu, s, o);
        if (t == 0) blkbase = s;
    }
    __syncthreads();

    // local inclusive scan of this block's 256 degrees
    int i = bid * 256 + t;
    int dg = (i < NN) ? g_degi[i] : 0;
    int sv = dg;
#pragma unroll
    for (int o = 1; o < 32; o <<= 1) {
        int u = __shfl_up_sync(0xffffffffu, sv, o);
        if (lane >= o) sv += u;
    }
    if (lane == 31) wtot[w] = sv;
    __syncthreads();
    if (w == 0) {
        int wv = (lane < 8) ? wtot[lane] : 0;
#pragma unroll
        for (int o = 1; o < 8; o <<= 1) {
            int u = __shfl_up_sync(0xffffffffu, wv, o);
            if (lane >= o) wv += u;
        }
        if (lane < 8) wpre[lane] = wv;
    }
    __syncthreads();
    int base = blkbase + ((w > 0) ? wpre[w - 1] : 0) + sv - dg;  // exclusive
    if (i < NN) {
        g_off[i]  = base;
        g_cur[i]  = base;
        g_dinv[i] = rsqrtf((float)(dg + 1));
    }
    if (bid == 0 && t < HH) { g_bnsum[t] = 0.f; g_bnsq[t] = 0.f; }
}

// ---------------- CSR fill ---------------------------------------------------
__global__ void __launch_bounds__(256) k_fill() {
    int e = blockIdx.x * 256 + threadIdx.x;
    if (e >= NE) return;
    int d = g_dst[e];
    int pos = atomicAdd(&g_cur[d], 1);
    g_csr[pos] = g_src[e];
}

// ---------------- GEMM1: hws = dinv * (x @ W1) -------------------------------
// 128 threads: 32 node-groups x 4 feat-groups; nodes strided 32 within thread
// so each unrolled step reads 8 CONSECUTIVE smem rows -> conflict-free.
#define TBN 256
#define KC  32
__global__ void __launch_bounds__(128) k_gemm1(const float* __restrict__ x,
                                               const float* __restrict__ W1) {
    __shared__ float xs[TBN][KC + 1];
    __shared__ float w1c[KC * HH];

    const int tid = threadIdx.x;
    const int ft  = tid & 3;
    const int nt  = tid >> 2;           // 0..31
    const int n0  = blockIdx.x * TBN;

    float acc[8][4];
#pragma unroll
    for (int i = 0; i < 8; i++)
#pragma unroll
        for (int j = 0; j < 4; j++) acc[i][j] = 0.f;

    for (int kc = 0; kc < FI; kc += KC) {
        __syncthreads();
#pragma unroll
        for (int i = 0; i < 16; i++) {
            int el4 = tid + i * 128;
            int nl  = el4 >> 3;
            int k4  = el4 & 7;
            int gn  = n0 + nl;
            float4 v = make_float4(0.f, 0.f, 0.f, 0.f);
            if (gn < NN)
                v = ((const float4*)(x + (size_t)gn * FI + kc))[k4];
            xs[nl][k4 * 4 + 0] = v.x;
            xs[nl][k4 * 4 + 1] = v.y;
            xs[nl][k4 * 4 + 2] = v.z;
            xs[nl][k4 * 4 + 3] = v.w;
        }
#pragma unroll
        for (int i = 0; i < 4; i++) {
            int el = tid + i * 128;
            w1c[el] = W1[kc * HH + el];
        }
        __syncthreads();

#pragma unroll
        for (int k = 0; k < KC; k++) {
            float4 w = *(const float4*)&w1c[k * HH + ft * 4];
#pragma unroll
            for (int i = 0; i < 8; i++) {
                float xv = xs[nt + 32 * i][k];   // 8 consecutive rows per step
                acc[i][0] += xv * w.x;
                acc[i][1] += xv * w.y;
                acc[i][2] += xv * w.z;
                acc[i][3] += xv * w.w;
            }
        }
    }

#pragma unroll
    for (int i = 0; i < 8; i++) {
        int gn = n0 + nt + 32 * i;
        if (gn < NN) {
            float di = g_dinv[gn];
            float4 v = make_float4(di * acc[i][0], di * acc[i][1],
                                   di * acc[i][2], di * acc[i][3]);
            *(float4*)(g_hws + (size_t)gn * HH + ft * 4) = v;
        }
    }
}

// ---------------- agg1: gather over CSR (no atomics) + BN stats --------------
// 4 threads per node (one float4 group each); CSR reads are quad-broadcast.
// BN partials reduced across warp by butterfly; atomics only from lanes 0-3.
__global__ void __launch_bounds__(256) k_agg1() {
    __shared__ float ssum[HH], ssq[HH];
    int tid = threadIdx.x;
    if (tid < HH) { ssum[tid] = 0.f; ssq[tid] = 0.f; }
    __syncthreads();

    int gt = blockIdx.x * 256 + tid;
    int n  = gt >> 2;
    int f  = gt & 3;
    float4 acc = make_float4(0.f, 0.f, 0.f, 0.f);
    if (n < NN) {
        acc = *(const float4*)(g_hws + (size_t)n * HH + f * 4); // self
        int beg = g_off[n];
        int cnt = g_degi[n];
        int k = 0;
        for (; k + 4 <= cnt; k += 4) {
            int s0 = g_csr[beg + k];
            int s1 = g_csr[beg + k + 1];
            int s2 = g_csr[beg + k + 2];
            int s3 = g_csr[beg + k + 3];
            float4 a = *(const float4*)(g_hws + (size_t)s0 * HH + f * 4);
            float4 b = *(const float4*)(g_hws + (size_t)s1 * HH + f * 4);
            float4 c = *(const float4*)(g_hws + (size_t)s2 * HH + f * 4);
            float4 d = *(const float4*)(g_hws + (size_t)s3 * HH + f * 4);
            acc.x += (a.x + b.x) + (c.x + d.x);
            acc.y += (a.y + b.y) + (c.y + d.y);
            acc.z += (a.z + b.z) + (c.z + d.z);
            acc.w += (a.w + b.w) + (c.w + d.w);
        }
        for (; k < cnt; k++) {
            int s = g_csr[beg + k];
            float4 a = *(const float4*)(g_hws + (size_t)s * HH + f * 4);
            acc.x += a.x; acc.y += a.y; acc.z += a.z; acc.w += a.w;
        }
        float di = g_dinv[n];
        acc.x *= di; acc.y *= di; acc.z *= di; acc.w *= di;
        *(float4*)(g_agg + (size_t)n * HH + f * 4) = acc;
    }
    // warp butterfly over lanes with the same f (distance 4,8,16); all lanes
    // are converged here (no early returns), out-of-range lanes carry zeros.
    float sx = acc.x * acc.x, sy = acc.y * acc.y,
          sz = acc.z * acc.z, sw = acc.w * acc.w;
#pragma unroll
    for (int o = 4; o < 32; o <<= 1) {
        acc.x += __shfl_xor_sync(0xffffffffu, acc.x, o);
        acc.y += __shfl_xor_sync(0xffffffffu, acc.y, o);
        acc.z += __shfl_xor_sync(0xffffffffu, acc.z, o);
        acc.w += __shfl_xor_sync(0xffffffffu, acc.w, o);
        sx    += __shfl_xor_sync(0xffffffffu, sx, o);
        sy    += __shfl_xor_sync(0xffffffffu, sy, o);
        sz    += __shfl_xor_sync(0xffffffffu, sz, o);
        sw    += __shfl_xor_sync(0xffffffffu, sw, o);
    }
    if ((tid & 31) < 4) {
        atomicAdd(&ssum[f * 4 + 0], acc.x);
        atomicAdd(&ssum[f * 4 + 1], acc.y);
        atomicAdd(&ssum[f * 4 + 2], acc.z);
        atomicAdd(&ssum[f * 4 + 3], acc.w);
        atomicAdd(&ssq [f * 4 + 0], sx);
        atomicAdd(&ssq [f * 4 + 1], sy);
        atomicAdd(&ssq [f * 4 + 2], sz);
        atomicAdd(&ssq [f * 4 + 3], sw);
    }
    __syncthreads();
    if (tid < HH) {
        atomicAdd(&g_bnsum[tid], ssum[tid]);
        atomicAdd(&g_bnsq[tid],  ssq[tid]);
    }
}

// ---------------- bn(inline) + relu + GEMM2: hw2s ----------------------------
// b1 cancels in BN (constant shift removed by mean subtraction).
__global__ void __launch_bounds__(256) k_fused2(const float* __restrict__ gamma,
                                                const float* __restrict__ beta,
                                                const float* __restrict__ W2) {
    __shared__ float a[HH], b[HH], w2[HH * 2];
    int tid = threadIdx.x;
    if (tid < HH) {
        float mean = g_bnsum[tid] / (float)NN;
        float var  = g_bnsq[tid] / (float)NN - mean * mean;
        float av   = gamma[tid] * rsqrtf(var + BN_EPS);
        a[tid] = av;
        b[tid] = beta[tid] - mean * av;
    }
    if (tid < HH * 2) w2[tid] = W2[tid];
    __syncthreads();
    int n = blockIdx.x * 256 + tid;
    if (n >= NN) return;
    const float4* hp = (const float4*)(g_agg + (size_t)n * HH);
    float acc0 = 0.f, acc1 = 0.f;
#pragma unroll
    for (int p = 0; p < 4; p++) {
        float4 h = hp[p];
        float v0 = fmaxf(a[p * 4 + 0] * h.x + b[p * 4 + 0], 0.f);
        float v1 = fmaxf(a[p * 4 + 1] * h.y + b[p * 4 + 1], 0.f);
        float v2 = fmaxf(a[p * 4 + 2] * h.z + b[p * 4 + 2], 0.f);
        float v3 = fmaxf(a[p * 4 + 3] * h.w + b[p * 4 + 3], 0.f);
        acc0 += v0 * w2[(p * 4 + 0) * 2] + v1 * w2[(p * 4 + 1) * 2]
              + v2 * w2[(p * 4 + 2) * 2] + v3 * w2[(p * 4 + 3) * 2];
        acc1 += v0 * w2[(p * 4 + 0) * 2 + 1] + v1 * w2[(p * 4 + 1) * 2 + 1]
              + v2 * w2[(p * 4 + 2) * 2 + 1] + v3 * w2[(p * 4 + 3) * 2 + 1];
    }
    float di = g_dinv[n];
    g_hw2s[2 * n]     = di * acc0;
    g_hw2s[2 * n + 1] = di * acc1;
}

// ---------------- layer2 gather + bias + log_softmax -> out ------------------
__global__ void __launch_bounds__(256) k_out(const float* __restrict__ b2,
                                             float* __restrict__ out) {
    int gt = blockIdx.x * 256 + threadIdx.x;
    int n  = gt >> 2;
    int q  = gt & 3;
    float ax = 0.f, ay = 0.f;
    if (n < NN) {
        int beg = g_off[n];
        int cnt = g_degi[n];
        if (q == 0) {   // self term once
            float2 v = ((const float2*)g_hw2s)[n];
            ax = v.x; ay = v.y;
        }
        for (int k = q; k < cnt; k += 4) {
            int s = g_csr[beg + k];
            float2 v = ((const float2*)g_hw2s)[s];
            ax += v.x; ay += v.y;
        }
    }
    // all lanes converged; quad lanes live in one warp
    ax += __shfl_xor_sync(0xffffffffu, ax, 1);
    ay += __shfl_xor_sync(0xffffffffu, ay, 1);
    ax += __shfl_xor_sync(0xffffffffu, ax, 2);
    ay += __shfl_xor_sync(0xffffffffu, ay, 2);
    if (n < NN && q == 0) {
        float di = g_dinv[n];
        float z0 = di * ax + b2[0];
        float z1 = di * ay + b2[1];
        float m  = fmaxf(z0, z1);
        float l  = m + logf(expf(z0 - m) + expf(z1 - m));
        out[2 * n]     = z0 - l;
        out[2 * n + 1] = z1 - l;
    }
}

// ---------------- launcher ---------------------------------------------------
extern "C" void kernel_launch(void* const* d_in, const int* in_sizes, int n_in,
                              void* d_out, int out_size) {
    const float* x     = (const float*)d_in[0];
    const void*  ei    = d_in[1];                  // int32 or int64, detected on device
    const float* W1    = (const float*)d_in[2];
    // d_in[3] = b1 : cancels under BN mean subtraction
    const float* gamma = (const float*)d_in[4];
    const float* beta  = (const float*)d_in[5];
    const float* W2    = (const float*)d_in[6];
    const float* b2    = (const float*)d_in[7];
    float* out = (float*)d_out;

    k_setup       <<<NBLK, 256>>>((const int*)ei);
    k_edge_pass1  <<<(NE / 2 + 255) / 256, 256>>>(ei);
    k_scan_partial<<<NBLK, 256>>>();
    k_scan_write  <<<NBLK, 256>>>();
    k_fill        <<<(NE + 255) / 256, 256>>>();
    k_gemm1       <<<(NN + TBN - 1) / TBN, 128>>>(x, W1);
    k_agg1        <<<(NN * 4 + 255) / 256, 256>>>();
    k_fused2      <<<NBLK, 256>>>(gamma, beta, W2);
    k_out         <<<(NN * 4 + 255) / 256, 256>>>(b2, out);
}